// round 10
// baseline (speedup 1.0000x reference)
#include <cuda_runtime.h>

#define FULLMASK 0xffffffffu
typedef unsigned long long u64;

constexpr int NPB  = 8;           // nodes (=warps) per block
constexpr int CH   = 320;         // edge-chunk capacity (8 nodes avg 200, +8 sigma)
constexpr int MAXN = 50001;

__device__ int   g_starts[MAXN];
__device__ float g_a1[(MAXN - 1) * 8];

// ---------- packed f32x2 helpers ----------
__device__ __forceinline__ u64 pack2(float lo, float hi) {
    u64 r; asm("mov.b64 %0,{%1,%2};" : "=l"(r) : "f"(lo), "f"(hi)); return r;
}
__device__ __forceinline__ u64 splat2(float v) {
    u64 r; asm("mov.b64 %0,{%1,%1};" : "=l"(r) : "f"(v)); return r;
}
__device__ __forceinline__ void unpack2(u64 v, float& lo, float& hi) {
    asm("mov.b64 {%0,%1},%2;" : "=f"(lo), "=f"(hi) : "l"(v));
}
__device__ __forceinline__ u64 fma2(u64 a, u64 b, u64 c) {
    u64 d; asm("fma.rn.f32x2 %0,%1,%2,%3;" : "=l"(d) : "l"(a), "l"(b), "l"(c)); return d;
}
__device__ __forceinline__ u64 add2(u64 a, u64 b) {
    u64 d; asm("add.rn.f32x2 %0,%1,%2;" : "=l"(d) : "l"(a), "l"(b)); return d;
}
__device__ __forceinline__ float elu1(float x) {
    return x > 0.0f ? x : (__expf(x) - 1.0f);
}

// ---------- kernel 0: CSR row starts ----------
__global__ void build_starts_kernel(const int* __restrict__ seg, int N, int E) {
    int e = blockIdx.x * blockDim.x + threadIdx.x;
    if (e >= E) return;
    int s = seg[e];
    int p = (e == 0) ? -1 : seg[e - 1];
    for (int n = p + 1; n <= s; ++n) g_starts[n] = e;
    if (e == E - 1)
        for (int n = s + 1; n <= N; ++n) g_starts[n] = E;
}

// 32-lane reduce of 8 partials; lane ends with head lane>>2
__device__ __forceinline__ float reduce8_32(const float p[8], int lane) {
    bool b4 = (lane & 16) != 0;
    float q[4];
#pragma unroll
    for (int j = 0; j < 4; ++j) {
        float send = b4 ? p[j] : p[j + 4];
        float recv = __shfl_xor_sync(FULLMASK, send, 16);
        q[j] = (b4 ? p[j + 4] : p[j]) + recv;
    }
    bool b3 = (lane & 8) != 0;
    float r[2];
#pragma unroll
    for (int j = 0; j < 2; ++j) {
        float send = b3 ? q[j] : q[j + 2];
        float recv = __shfl_xor_sync(FULLMASK, send, 8);
        r[j] = (b3 ? q[j + 2] : q[j]) + recv;
    }
    bool b2 = (lane & 4) != 0;
    float send = b2 ? r[0] : r[1];
    float recv = __shfl_xor_sync(FULLMASK, send, 4);
    float s = (b2 ? r[1] : r[0]) + recv;
    s += __shfl_xor_sync(FULLMASK, s, 2);
    s += __shfl_xor_sync(FULLMASK, s, 1);
    return s;
}

// ---------- kernel 1: a1[n,h] = features[n] . attn1[h] ----------
__global__ __launch_bounds__(256, 8)
void a1_kernel(const float* __restrict__ features,
               const float* __restrict__ attn1, int N) {
    const int lane = threadIdx.x & 31;
    const int n = blockIdx.x * 8 + (threadIdx.x >> 5);
    if (n >= N) return;
    float2 f = *(const float2*)(features + (size_t)n * 64 + 2 * lane);
    float p1[8];
#pragma unroll
    for (int h = 0; h < 8; ++h) {
        float2 a = *(const float2*)(attn1 + h * 64 + 2 * lane);
        p1[h] = f.x * a.x + f.y * a.y;
    }
    float v = reduce8_32(p1, lane);
    if ((lane & 3) == 0) g_a1[n * 8 + (lane >> 2)] = v;
}

// ---------- main kernel: block = 8 warps = 8 nodes; two-phase, shuffle-free ----------
__global__ __launch_bounds__(256, 4)
void gat_main_kernel(const float* __restrict__ emb,
                     const float* __restrict__ attn2,
                     const int*   __restrict__ seg,
                     float*       __restrict__ out,
                     int N)
{
    __shared__ float4 s_stage[NPB][16][16];   // [warp][edge][chunk], chunk idx swizzled (32KB)
    __shared__ float  s_w[CH * 8];            // per-edge weights (10KB)
    __shared__ float4 s_a2[8][16];            // attn2 [head][16B-chunk] (2KB)

    const int tid  = threadIdx.x;
    const int lane = tid & 31;
    const int wid  = tid >> 5;

    // attn2 -> smem (128 float4s)
    if (tid < 128) {
        const float4* a2f4 = (const float4*)attn2;
        s_a2[tid >> 4][tid & 15] = a2f4[tid];
    }

    const int nb0 = blockIdx.x * NPB;
    if (nb0 >= N) return;
    const int eStart = g_starts[nb0];
    const int eEnd   = g_starts[min(nb0 + NPB, N)];

    const int n  = nb0 + wid;                 // this warp's node
    const bool nodeValid = n < N;
    const int s0 = nodeValid ? g_starts[n]     : 0;
    const int e0 = nodeValid ? g_starts[n + 1] : 0;

    const float4* __restrict__ ef4  = (const float4*)emb;
    const float2* __restrict__ emb2 = (const float2*)emb;

    const u64 Z = 0ull;
    u64 accx[4], accy[4], dnp[4];             // head-pair packed accumulators
#pragma unroll
    for (int hp = 0; hp < 4; ++hp) { accx[hp] = Z; accy[hp] = Z; dnp[hp] = Z; }

    __syncthreads();                          // s_a2 ready

    const int el = lane & 15;                 // score phase: this lane's edge slot
    const int hh = lane >> 4;                 //              head half (0:0-3, 1:4-7)

    for (int cb = eStart; cb < eEnd; cb += CH) {
        const int ce = min(cb + CH, eEnd);
        const int nSweeps = (ce - cb + 15) >> 4;

        // ======== score phase: warp-strided sweeps of 16 edges ========
        for (int s = wid; s < nSweeps; s += NPB) {
            const int eb = cb + s * 16;

            // fill staging: 16 edges x 256B, coalesced, swizzled store
#pragma unroll
            for (int it = 0; it < 8; ++it) {
                int idx = it * 32 + lane;
                int e = idx >> 4, c = idx & 15;
                int ge = min(eb + e, eEnd - 1);
                s_stage[wid][e][c ^ e] = ef4[(size_t)ge * 16 + c];
            }
            __syncwarp();

            // in-lane dot: edge el, heads [4hh, 4hh+4), all 64 dims
            const int ge  = eb + el;
            const int gec = min(ge, eEnd - 1);
            const int sg  = seg[gec];
            float4 a1v = *(const float4*)(g_a1 + sg * 8 + hh * 4);

            u64 d0 = Z, d1 = Z, d2 = Z, d3 = Z;
#pragma unroll
            for (int c = 0; c < 16; ++c) {
                float4 ev = s_stage[wid][el][c ^ el];
                u64 ep0 = pack2(ev.x, ev.y), ep1 = pack2(ev.z, ev.w);
                float4 a20 = s_a2[hh * 4 + 0][c];
                float4 a21 = s_a2[hh * 4 + 1][c];
                float4 a22 = s_a2[hh * 4 + 2][c];
                float4 a23 = s_a2[hh * 4 + 3][c];
                d0 = fma2(ep0, pack2(a20.x, a20.y), d0);
                d1 = fma2(ep0, pack2(a21.x, a21.y), d1);
                d2 = fma2(ep0, pack2(a22.x, a22.y), d2);
                d3 = fma2(ep0, pack2(a23.x, a23.y), d3);
                d0 = fma2(ep1, pack2(a20.z, a20.w), d0);
                d1 = fma2(ep1, pack2(a21.z, a21.w), d1);
                d2 = fma2(ep1, pack2(a22.z, a22.w), d2);
                d3 = fma2(ep1, pack2(a23.z, a23.w), d3);
            }
            float l0, h0, l1, h1, l2, h2, l3, h3;
            unpack2(d0, l0, h0); unpack2(d1, l1, h1);
            unpack2(d2, l2, h2); unpack2(d3, l3, h3);
            float sc0 = a1v.x + (l0 + h0);
            float sc1 = a1v.y + (l1 + h1);
            float sc2 = a1v.z + (l2 + h2);
            float sc3 = a1v.w + (l3 + h3);
            sc0 = fmaxf(sc0, 0.2f * sc0);
            sc1 = fmaxf(sc1, 0.2f * sc1);
            sc2 = fmaxf(sc2, 0.2f * sc2);
            sc3 = fmaxf(sc3, 0.2f * sc3);
            // no-max softmax: scores bounded, exp cannot overflow fp32
            float4 wv = make_float4(__expf(sc0), __expf(sc1), __expf(sc2), __expf(sc3));
            *(float4*)(s_w + (s * 16 + el) * 8 + hh * 4) = wv;
        }
        __syncthreads();

        // ======== agg phase: warp per node, edges in [cb, ce), 2-deep pipeline ========
        if (nodeValid) {
            const int lo  = max(s0, cb);
            const int hiE = min(e0, ce);
            if (lo < hiE) {
                float2 cv0 = emb2[(size_t)lo * 32 + lane];
                float4 wa0 = *(const float4*)(s_w + (lo - cb) * 8);
                float4 wb0 = *(const float4*)(s_w + (lo - cb) * 8 + 4);
                for (int e = lo; e < hiE; ++e) {
                    float2 cv1; float4 wa1, wb1;
                    if (e + 1 < hiE) {                 // prefetch next edge
                        cv1 = emb2[(size_t)(e + 1) * 32 + lane];
                        wa1 = *(const float4*)(s_w + (e + 1 - cb) * 8);
                        wb1 = *(const float4*)(s_w + (e + 1 - cb) * 8 + 4);
                    }
                    u64 w01 = pack2(wa0.x, wa0.y), w23 = pack2(wa0.z, wa0.w);
                    u64 w45 = pack2(wb0.x, wb0.y), w67 = pack2(wb0.z, wb0.w);
                    dnp[0] = add2(dnp[0], w01);
                    dnp[1] = add2(dnp[1], w23);
                    dnp[2] = add2(dnp[2], w45);
                    dnp[3] = add2(dnp[3], w67);
                    u64 cx = splat2(cv0.x), cy = splat2(cv0.y);
                    accx[0] = fma2(w01, cx, accx[0]);  accy[0] = fma2(w01, cy, accy[0]);
                    accx[1] = fma2(w23, cx, accx[1]);  accy[1] = fma2(w23, cy, accy[1]);
                    accx[2] = fma2(w45, cx, accx[2]);  accy[2] = fma2(w45, cy, accy[2]);
                    accx[3] = fma2(w67, cx, accx[3]);  accy[3] = fma2(w67, cy, accy[3]);
                    cv0 = cv1; wa0 = wa1; wb0 = wb1;
                }
            }
        }
        __syncthreads();                       // s_w reused next chunk
    }

    // ======== finalize: normalize, ELU, store ========
    if (nodeValid) {
        float* op = out + (size_t)n * 512 + 2 * lane;
#pragma unroll
        for (int hp = 0; hp < 4; ++hp) {
            float dA, dB; unpack2(dnp[hp], dA, dB);
            float iA = dA > 0.0f ? __frcp_rn(dA) : 1.0f;
            float iB = dB > 0.0f ? __frcp_rn(dB) : 1.0f;
            float xA, xB, yA, yB;
            unpack2(accx[hp], xA, xB);
            unpack2(accy[hp], yA, yB);
            *(float2*)(op + (2 * hp)     * 64) = make_float2(elu1(xA * iA), elu1(yA * iA));
            *(float2*)(op + (2 * hp + 1) * 64) = make_float2(elu1(xB * iB), elu1(yB * iB));
        }
    }
}

extern "C" void kernel_launch(void* const* d_in, const int* in_sizes, int n_in,
                              void* d_out, int out_size) {
    const float* features = (const float*)d_in[0];
    const float* emb      = (const float*)d_in[1];
    const float* attn1    = (const float*)d_in[2];
    const float* attn2    = (const float*)d_in[3];
    const int*   seg      = (const int*)d_in[4];
    float* out = (float*)d_out;

    int N = in_sizes[0] / 64;    // 50000
    int E = in_sizes[4];         // 1250000

    build_starts_kernel<<<(E + 255) / 256, 256>>>(seg, N, E);
    a1_kernel<<<(N + 7) / 8, 256>>>(features, attn1, N);

    int blocks = (N + NPB - 1) / NPB;
    gat_main_kernel<<<blocks, NPB * 32>>>(emb, attn2, seg, out, N);
}

// round 11
// speedup vs baseline: 1.2295x; 1.2295x over previous
#include <cuda_runtime.h>

#define FULLMASK 0xffffffffu
typedef unsigned long long u64;

constexpr int NPB  = 4;           // nodes (=warps) per block
constexpr int CH   = 192;         // edge-chunk capacity (multiple of 16)
constexpr int MAXN = 50001;

__device__ int   g_starts[MAXN];
__device__ float g_a1[(MAXN - 1) * 8];

// ---------- packed f32x2 helpers ----------
__device__ __forceinline__ u64 pack2(float lo, float hi) {
    u64 r; asm("mov.b64 %0,{%1,%2};" : "=l"(r) : "f"(lo), "f"(hi)); return r;
}
__device__ __forceinline__ u64 splat2(float v) {
    u64 r; asm("mov.b64 %0,{%1,%1};" : "=l"(r) : "f"(v)); return r;
}
__device__ __forceinline__ void unpack2(u64 v, float& lo, float& hi) {
    asm("mov.b64 {%0,%1},%2;" : "=f"(lo), "=f"(hi) : "l"(v));
}
__device__ __forceinline__ u64 fma2(u64 a, u64 b, u64 c) {
    u64 d; asm("fma.rn.f32x2 %0,%1,%2,%3;" : "=l"(d) : "l"(a), "l"(b), "l"(c)); return d;
}
__device__ __forceinline__ u64 add2(u64 a, u64 b) {
    u64 d; asm("add.rn.f32x2 %0,%1,%2;" : "=l"(d) : "l"(a), "l"(b)); return d;
}
__device__ __forceinline__ float elu1(float x) {
    return x > 0.0f ? x : (__expf(x) - 1.0f);
}

// ---------- kernel 0: CSR row starts ----------
__global__ void build_starts_kernel(const int* __restrict__ seg, int N, int E) {
    int e = blockIdx.x * blockDim.x + threadIdx.x;
    if (e >= E) return;
    int s = seg[e];
    int p = (e == 0) ? -1 : seg[e - 1];
    for (int n = p + 1; n <= s; ++n) g_starts[n] = e;
    if (e == E - 1)
        for (int n = s + 1; n <= N; ++n) g_starts[n] = E;
}

// 32-lane reduce of 8 partials; lane ends with head lane>>2
__device__ __forceinline__ float reduce8_32(const float p[8], int lane) {
    bool b4 = (lane & 16) != 0;
    float q[4];
#pragma unroll
    for (int j = 0; j < 4; ++j) {
        float send = b4 ? p[j] : p[j + 4];
        float recv = __shfl_xor_sync(FULLMASK, send, 16);
        q[j] = (b4 ? p[j + 4] : p[j]) + recv;
    }
    bool b3 = (lane & 8) != 0;
    float r[2];
#pragma unroll
    for (int j = 0; j < 2; ++j) {
        float send = b3 ? q[j] : q[j + 2];
        float recv = __shfl_xor_sync(FULLMASK, send, 8);
        r[j] = (b3 ? q[j + 2] : q[j]) + recv;
    }
    bool b2 = (lane & 4) != 0;
    float send = b2 ? r[0] : r[1];
    float recv = __shfl_xor_sync(FULLMASK, send, 4);
    float s = (b2 ? r[1] : r[0]) + recv;
    s += __shfl_xor_sync(FULLMASK, s, 2);
    s += __shfl_xor_sync(FULLMASK, s, 1);
    return s;
}

// ---------- kernel 1: a1[n,h] = features[n] . attn1[h] ----------
__global__ __launch_bounds__(256, 8)
void a1_kernel(const float* __restrict__ features,
               const float* __restrict__ attn1, int N) {
    const int lane = threadIdx.x & 31;
    const int n = blockIdx.x * 8 + (threadIdx.x >> 5);
    if (n >= N) return;
    float2 f = *(const float2*)(features + (size_t)n * 64 + 2 * lane);
    float p1[8];
#pragma unroll
    for (int h = 0; h < 8; ++h) {
        float2 a = *(const float2*)(attn1 + h * 64 + 2 * lane);
        p1[h] = f.x * a.x + f.y * a.y;
    }
    float v = reduce8_32(p1, lane);
    if ((lane & 3) == 0) g_a1[n * 8 + (lane >> 2)] = v;
}

// ---------- main kernel: block = 4 warps = 4 nodes; two-phase, shuffle-free ----------
__global__ __launch_bounds__(128, 8)
void gat_main_kernel(const float* __restrict__ emb,
                     const float* __restrict__ attn2,
                     const int*   __restrict__ seg,
                     float*       __restrict__ out,
                     int N)
{
    __shared__ float4 s_stage[NPB][16][16];   // [warp][edge][chunk], chunk idx swizzled (16KB)
    __shared__ float  s_w[CH * 8];            // per-edge weights (6KB)
    __shared__ float4 s_a2[8][16];            // attn2 [head][16B-chunk] (2KB)

    const int tid  = threadIdx.x;
    const int lane = tid & 31;
    const int wid  = tid >> 5;

    // attn2 -> smem (128 float4s, one per thread)
    {
        const float4* a2f4 = (const float4*)attn2;
        s_a2[tid >> 4][tid & 15] = a2f4[tid];
    }

    const int nb0 = blockIdx.x * NPB;
    if (nb0 >= N) return;
    const int eStart = g_starts[nb0];
    const int eEnd   = g_starts[min(nb0 + NPB, N)];

    const int n  = nb0 + wid;                 // this warp's node
    const bool nodeValid = n < N;
    const int s0 = nodeValid ? g_starts[n]     : 0;
    const int e0 = nodeValid ? g_starts[n + 1] : 0;

    const float4* __restrict__ ef4  = (const float4*)emb;
    const float2* __restrict__ emb2 = (const float2*)emb;

    const u64 Z = 0ull;
    u64 accx[4], accy[4], dnp[4];             // head-pair packed accumulators
#pragma unroll
    for (int hp = 0; hp < 4; ++hp) { accx[hp] = Z; accy[hp] = Z; dnp[hp] = Z; }

    __syncthreads();                          // s_a2 ready

    const int el = lane & 15;                 // score phase: this lane's edge slot
    const int hh = lane >> 4;                 //              head half (0:0-3, 1:4-7)

    for (int cb = eStart; cb < eEnd; cb += CH) {
        const int ce = min(cb + CH, eEnd);
        const int nSweeps = (ce - cb + 15) >> 4;

        // ======== score phase: warp-strided sweeps of 16 edges ========
        for (int s = wid; s < nSweeps; s += NPB) {
            const int eb = cb + s * 16;

            // fill staging: 16 edges x 256B, coalesced, swizzled store
#pragma unroll
            for (int it = 0; it < 8; ++it) {
                int idx = it * 32 + lane;
                int e = idx >> 4, c = idx & 15;
                int ge = min(eb + e, eEnd - 1);
                s_stage[wid][e][c ^ e] = ef4[(size_t)ge * 16 + c];
            }
            __syncwarp();

            // in-lane dot: edge el, heads [4hh, 4hh+4), all 64 dims
            const int ge  = eb + el;
            const int gec = min(ge, eEnd - 1);
            const int sg  = seg[gec];
            float4 a1v = *(const float4*)(g_a1 + sg * 8 + hh * 4);

            u64 d0 = Z, d1 = Z, d2 = Z, d3 = Z;
#pragma unroll
            for (int c = 0; c < 16; ++c) {
                // direct u64-pair views of 16B-aligned smem: LDS.128 feeds fma2 w/o MOVs
                const u64* evp = (const u64*)&s_stage[wid][el][c ^ el];
                u64 ep0 = evp[0], ep1 = evp[1];
                const u64* a0p = (const u64*)&s_a2[hh * 4 + 0][c];
                const u64* a1p = (const u64*)&s_a2[hh * 4 + 1][c];
                const u64* a2p = (const u64*)&s_a2[hh * 4 + 2][c];
                const u64* a3p = (const u64*)&s_a2[hh * 4 + 3][c];
                d0 = fma2(ep0, a0p[0], d0);
                d1 = fma2(ep0, a1p[0], d1);
                d2 = fma2(ep0, a2p[0], d2);
                d3 = fma2(ep0, a3p[0], d3);
                d0 = fma2(ep1, a0p[1], d0);
                d1 = fma2(ep1, a1p[1], d1);
                d2 = fma2(ep1, a2p[1], d2);
                d3 = fma2(ep1, a3p[1], d3);
            }
            float l0, h0, l1, h1, l2, h2, l3, h3;
            unpack2(d0, l0, h0); unpack2(d1, l1, h1);
            unpack2(d2, l2, h2); unpack2(d3, l3, h3);
            float sc0 = a1v.x + (l0 + h0);
            float sc1 = a1v.y + (l1 + h1);
            float sc2 = a1v.z + (l2 + h2);
            float sc3 = a1v.w + (l3 + h3);
            sc0 = fmaxf(sc0, 0.2f * sc0);
            sc1 = fmaxf(sc1, 0.2f * sc1);
            sc2 = fmaxf(sc2, 0.2f * sc2);
            sc3 = fmaxf(sc3, 0.2f * sc3);
            // no-max softmax: scores bounded, exp cannot overflow fp32
            float4 wv = make_float4(__expf(sc0), __expf(sc1), __expf(sc2), __expf(sc3));
            *(float4*)(s_w + (s * 16 + el) * 8 + hh * 4) = wv;
        }
        __syncthreads();

        // ======== agg phase: warp per node, edges in [cb, ce) ========
        if (nodeValid) {
            const int lo  = max(s0, cb);
            const int hiE = min(e0, ce);
            for (int e = lo; e < hiE; ++e) {
                const int eloc = e - cb;
                float2 cv = emb2[(size_t)e * 32 + lane];           // L1-hot (just staged)
                const u64* wp = (const u64*)(s_w + eloc * 8);      // broadcast LDS.128 x2
                u64 w01 = wp[0], w23 = wp[1], w45 = wp[2], w67 = wp[3];
                dnp[0] = add2(dnp[0], w01);
                dnp[1] = add2(dnp[1], w23);
                dnp[2] = add2(dnp[2], w45);
                dnp[3] = add2(dnp[3], w67);
                u64 cx = splat2(cv.x), cy = splat2(cv.y);
                accx[0] = fma2(w01, cx, accx[0]);  accy[0] = fma2(w01, cy, accy[0]);
                accx[1] = fma2(w23, cx, accx[1]);  accy[1] = fma2(w23, cy, accy[1]);
                accx[2] = fma2(w45, cx, accx[2]);  accy[2] = fma2(w45, cy, accy[2]);
                accx[3] = fma2(w67, cx, accx[3]);  accy[3] = fma2(w67, cy, accy[3]);
            }
        }
        __syncthreads();                       // s_w reused next chunk
    }

    // ======== finalize: normalize, ELU, store ========
    if (nodeValid) {
        float* op = out + (size_t)n * 512 + 2 * lane;
#pragma unroll
        for (int hp = 0; hp < 4; ++hp) {
            float dA, dB; unpack2(dnp[hp], dA, dB);
            float iA = dA > 0.0f ? __frcp_rn(dA) : 1.0f;
            float iB = dB > 0.0f ? __frcp_rn(dB) : 1.0f;
            float xA, xB, yA, yB;
            unpack2(accx[hp], xA, xB);
            unpack2(accy[hp], yA, yB);
            *(float2*)(op + (2 * hp)     * 64) = make_float2(elu1(xA * iA), elu1(yA * iA));
            *(float2*)(op + (2 * hp + 1) * 64) = make_float2(elu1(xB * iB), elu1(yB * iB));
        }
    }
}

extern "C" void kernel_launch(void* const* d_in, const int* in_sizes, int n_in,
                              void* d_out, int out_size) {
    const float* features = (const float*)d_in[0];
    const float* emb      = (const float*)d_in[1];
    const float* attn1    = (const float*)d_in[2];
    const float* attn2    = (const float*)d_in[3];
    const int*   seg      = (const int*)d_in[4];
    float* out = (float*)d_out;

    int N = in_sizes[0] / 64;    // 50000
    int E = in_sizes[4];         // 1250000

    build_starts_kernel<<<(E + 255) / 256, 256>>>(seg, N, E);
    a1_kernel<<<(N + 7) / 8, 256>>>(features, attn1, N);

    int blocks = (N + NPB - 1) / NPB;
    gat_main_kernel<<<blocks, NPB * 32>>>(emb, attn2, seg, out, N);
}

// round 12
// speedup vs baseline: 1.2508x; 1.0173x over previous
#include <cuda_runtime.h>

#define FULLMASK 0xffffffffu
typedef unsigned long long u64;

constexpr int NPB  = 4;           // nodes (=warps) per block
constexpr int CH   = 192;         // edge-chunk capacity (multiple of 16)
constexpr int MAXN = 50001;

__device__ int   g_starts[MAXN];
__device__ float g_a1[(MAXN - 1) * 8];

// ---------- packed f32x2 helpers ----------
__device__ __forceinline__ u64 pack2(float lo, float hi) {
    u64 r; asm("mov.b64 %0,{%1,%2};" : "=l"(r) : "f"(lo), "f"(hi)); return r;
}
__device__ __forceinline__ u64 splat2(float v) {
    u64 r; asm("mov.b64 %0,{%1,%1};" : "=l"(r) : "f"(v)); return r;
}
__device__ __forceinline__ void unpack2(u64 v, float& lo, float& hi) {
    asm("mov.b64 {%0,%1},%2;" : "=f"(lo), "=f"(hi) : "l"(v));
}
__device__ __forceinline__ u64 fma2(u64 a, u64 b, u64 c) {
    u64 d; asm("fma.rn.f32x2 %0,%1,%2,%3;" : "=l"(d) : "l"(a), "l"(b), "l"(c)); return d;
}
__device__ __forceinline__ u64 add2(u64 a, u64 b) {
    u64 d; asm("add.rn.f32x2 %0,%1,%2;" : "=l"(d) : "l"(a), "l"(b)); return d;
}
__device__ __forceinline__ float elu1(float x) {
    return x > 0.0f ? x : (__expf(x) - 1.0f);
}

// 32-lane reduce of 8 partials; lane ends with head lane>>2
__device__ __forceinline__ float reduce8_32(const float p[8], int lane) {
    bool b4 = (lane & 16) != 0;
    float q[4];
#pragma unroll
    for (int j = 0; j < 4; ++j) {
        float send = b4 ? p[j] : p[j + 4];
        float recv = __shfl_xor_sync(FULLMASK, send, 16);
        q[j] = (b4 ? p[j + 4] : p[j]) + recv;
    }
    bool b3 = (lane & 8) != 0;
    float r[2];
#pragma unroll
    for (int j = 0; j < 2; ++j) {
        float send = b3 ? q[j] : q[j + 2];
        float recv = __shfl_xor_sync(FULLMASK, send, 8);
        r[j] = (b3 ? q[j + 2] : q[j]) + recv;
    }
    bool b2 = (lane & 4) != 0;
    float send = b2 ? r[0] : r[1];
    float recv = __shfl_xor_sync(FULLMASK, send, 4);
    float s = (b2 ? r[1] : r[0]) + recv;
    s += __shfl_xor_sync(FULLMASK, s, 2);
    s += __shfl_xor_sync(FULLMASK, s, 1);
    return s;
}

// ---------- prep kernel: CSR row starts (edge-parallel) + a1 (warp-per-node) ----------
__global__ __launch_bounds__(256, 8)
void prep_kernel(const int* __restrict__ seg,
                 const float* __restrict__ features,
                 const float* __restrict__ attn1,
                 int N, int E) {
    const int gtid = blockIdx.x * blockDim.x + threadIdx.x;

    // part 1: row starts
    if (gtid < E) {
        int s = seg[gtid];
        int p = (gtid == 0) ? -1 : seg[gtid - 1];
        for (int n = p + 1; n <= s; ++n) g_starts[n] = gtid;
        if (gtid == E - 1)
            for (int n = s + 1; n <= N; ++n) g_starts[n] = E;
    }

    // part 2: a1[n,h] = features[n] . attn1[h]   (one warp per node)
    const int lane = threadIdx.x & 31;
    const int n = gtid >> 5;
    if (n < N) {
        float2 f = *(const float2*)(features + (size_t)n * 64 + 2 * lane);
        float p1[8];
#pragma unroll
        for (int h = 0; h < 8; ++h) {
            float2 a = *(const float2*)(attn1 + h * 64 + 2 * lane);
            p1[h] = f.x * a.x + f.y * a.y;
        }
        float v = reduce8_32(p1, lane);
        if ((lane & 3) == 0) g_a1[n * 8 + (lane >> 2)] = v;
    }
}

// ---------- main kernel: block = 4 warps = 4 nodes; two-phase, shuffle-free ----------
__global__ __launch_bounds__(128, 8)
void gat_main_kernel(const float* __restrict__ emb,
                     const float* __restrict__ attn2,
                     const int*   __restrict__ seg,
                     float*       __restrict__ out,
                     int N)
{
    __shared__ float4 s_stage[NPB][16][16];   // [warp][edge][chunk], chunk idx swizzled (16KB)
    __shared__ float  s_w[CH * 8];            // per-edge weights (6KB)
    __shared__ float4 s_a2[8][16];            // attn2 [head][16B-chunk] (2KB)

    const int tid  = threadIdx.x;
    const int lane = tid & 31;
    const int wid  = tid >> 5;

    // attn2 -> smem (128 float4s, one per thread)
    {
        const float4* a2f4 = (const float4*)attn2;
        s_a2[tid >> 4][tid & 15] = a2f4[tid];
    }

    const int nb0 = blockIdx.x * NPB;
    if (nb0 >= N) return;
    const int eStart = g_starts[nb0];
    const int eEnd   = g_starts[min(nb0 + NPB, N)];

    const int n  = nb0 + wid;                 // this warp's node
    const bool nodeValid = n < N;
    const int s0 = nodeValid ? g_starts[n]     : 0;
    const int e0 = nodeValid ? g_starts[n + 1] : 0;

    const float4* __restrict__ ef4  = (const float4*)emb;
    const float2* __restrict__ emb2 = (const float2*)emb;

    const u64 Z = 0ull;
    u64 accx[4], accy[4], dnp[4];             // head-pair packed accumulators
#pragma unroll
    for (int hp = 0; hp < 4; ++hp) { accx[hp] = Z; accy[hp] = Z; dnp[hp] = Z; }

    __syncthreads();                          // s_a2 ready

    const int el = lane & 15;                 // score phase: this lane's edge slot
    const int hh = lane >> 4;                 //              head half (0:0-3, 1:4-7)

    for (int cb = eStart; cb < eEnd; cb += CH) {
        const int ce = min(cb + CH, eEnd);
        const int nSweeps = (ce - cb + 15) >> 4;

        // ======== score phase: warp-strided sweeps of 16 edges ========
        for (int s = wid; s < nSweeps; s += NPB) {
            const int eb = cb + s * 16;

            // fill staging: 16 edges x 256B, coalesced, swizzled store
#pragma unroll
            for (int it = 0; it < 8; ++it) {
                int idx = it * 32 + lane;
                int e = idx >> 4, c = idx & 15;
                int ge = min(eb + e, eEnd - 1);
                s_stage[wid][e][c ^ e] = ef4[(size_t)ge * 16 + c];
            }
            __syncwarp();

            // in-lane dot: edge el, heads [4hh, 4hh+4), all 64 dims
            const int ge  = eb + el;
            const int gec = min(ge, eEnd - 1);
            const int sg  = seg[gec];
            float4 a1v = *(const float4*)(g_a1 + sg * 8 + hh * 4);

            u64 d0 = Z, d1 = Z, d2 = Z, d3 = Z;
#pragma unroll
            for (int c = 0; c < 16; ++c) {
                float4 ev = s_stage[wid][el][c ^ el];
                u64 ep0 = pack2(ev.x, ev.y), ep1 = pack2(ev.z, ev.w);
                float4 a20 = s_a2[hh * 4 + 0][c];
                float4 a21 = s_a2[hh * 4 + 1][c];
                float4 a22 = s_a2[hh * 4 + 2][c];
                float4 a23 = s_a2[hh * 4 + 3][c];
                d0 = fma2(ep0, pack2(a20.x, a20.y), d0);
                d1 = fma2(ep0, pack2(a21.x, a21.y), d1);
                d2 = fma2(ep0, pack2(a22.x, a22.y), d2);
                d3 = fma2(ep0, pack2(a23.x, a23.y), d3);
                d0 = fma2(ep1, pack2(a20.z, a20.w), d0);
                d1 = fma2(ep1, pack2(a21.z, a21.w), d1);
                d2 = fma2(ep1, pack2(a22.z, a22.w), d2);
                d3 = fma2(ep1, pack2(a23.z, a23.w), d3);
            }
            float l0, h0, l1, h1, l2, h2, l3, h3;
            unpack2(d0, l0, h0); unpack2(d1, l1, h1);
            unpack2(d2, l2, h2); unpack2(d3, l3, h3);
            float sc0 = a1v.x + (l0 + h0);
            float sc1 = a1v.y + (l1 + h1);
            float sc2 = a1v.z + (l2 + h2);
            float sc3 = a1v.w + (l3 + h3);
            sc0 = fmaxf(sc0, 0.2f * sc0);
            sc1 = fmaxf(sc1, 0.2f * sc1);
            sc2 = fmaxf(sc2, 0.2f * sc2);
            sc3 = fmaxf(sc3, 0.2f * sc3);
            // no-max softmax: scores bounded, exp cannot overflow fp32
            float4 wv = make_float4(__expf(sc0), __expf(sc1), __expf(sc2), __expf(sc3));
            *(float4*)(s_w + (s * 16 + el) * 8 + hh * 4) = wv;
        }
        __syncthreads();

        // ======== agg phase: warp per node, edges in [cb, ce) ========
        if (nodeValid) {
            const int lo  = max(s0, cb);
            const int hiE = min(e0, ce);
            for (int e = lo; e < hiE; ++e) {
                const int eloc = e - cb;
                float2 cv = emb2[(size_t)e * 32 + lane];           // L1-hot (just staged)
                float4 wa = *(const float4*)(s_w + eloc * 8);      // broadcast LDS.128
                float4 wb = *(const float4*)(s_w + eloc * 8 + 4);
                u64 w01 = pack2(wa.x, wa.y), w23 = pack2(wa.z, wa.w);
                u64 w45 = pack2(wb.x, wb.y), w67 = pack2(wb.z, wb.w);
                dnp[0] = add2(dnp[0], w01);
                dnp[1] = add2(dnp[1], w23);
                dnp[2] = add2(dnp[2], w45);
                dnp[3] = add2(dnp[3], w67);
                u64 cx = splat2(cv.x), cy = splat2(cv.y);
                accx[0] = fma2(w01, cx, accx[0]);  accy[0] = fma2(w01, cy, accy[0]);
                accx[1] = fma2(w23, cx, accx[1]);  accy[1] = fma2(w23, cy, accy[1]);
                accx[2] = fma2(w45, cx, accx[2]);  accy[2] = fma2(w45, cy, accy[2]);
                accx[3] = fma2(w67, cx, accx[3]);  accy[3] = fma2(w67, cy, accy[3]);
            }
        }
        __syncthreads();                       // s_w reused next chunk
    }

    // ======== finalize: normalize, ELU, store ========
    if (nodeValid) {
        float* op = out + (size_t)n * 512 + 2 * lane;
#pragma unroll
        for (int hp = 0; hp < 4; ++hp) {
            float dA, dB; unpack2(dnp[hp], dA, dB);
            float iA = dA > 0.0f ? __frcp_rn(dA) : 1.0f;
            float iB = dB > 0.0f ? __frcp_rn(dB) : 1.0f;
            float xA, xB, yA, yB;
            unpack2(accx[hp], xA, xB);
            unpack2(accy[hp], yA, yB);
            *(float2*)(op + (2 * hp)     * 64) = make_float2(elu1(xA * iA), elu1(yA * iA));
            *(float2*)(op + (2 * hp + 1) * 64) = make_float2(elu1(xB * iB), elu1(yB * iB));
        }
    }
}

extern "C" void kernel_launch(void* const* d_in, const int* in_sizes, int n_in,
                              void* d_out, int out_size) {
    const float* features = (const float*)d_in[0];
    const float* emb      = (const float*)d_in[1];
    const float* attn1    = (const float*)d_in[2];
    const float* attn2    = (const float*)d_in[3];
    const int*   seg      = (const int*)d_in[4];
    float* out = (float*)d_out;

    int N = in_sizes[0] / 64;    // 50000
    int E = in_sizes[4];         // 1250000

    // prep covers both edge-parallel starts (E threads) and warp-per-node a1 (N*32 threads)
    int prepThreads = (N * 32 > E) ? N * 32 : E;
    prep_kernel<<<(prepThreads + 255) / 256, 256>>>(seg, features, attn1, N, E);

    int blocks = (N + NPB - 1) / NPB;
    gat_main_kernel<<<blocks, NPB * 32>>>(emb, attn2, seg, out, N);
}

// round 13
// speedup vs baseline: 1.3490x; 1.0786x over previous
#include <cuda_runtime.h>

#define FULLMASK 0xffffffffu
typedef unsigned long long u64;

constexpr int NPB  = 4;           // nodes (=warps) per block
constexpr int MAXN = 50001;

__device__ int   g_starts[MAXN];
__device__ float g_a1[(MAXN - 1) * 8];

// ---------- packed f32x2 helpers ----------
__device__ __forceinline__ u64 pack2(float lo, float hi) {
    u64 r; asm("mov.b64 %0,{%1,%2};" : "=l"(r) : "f"(lo), "f"(hi)); return r;
}
__device__ __forceinline__ u64 splat2(float v) {
    u64 r; asm("mov.b64 %0,{%1,%1};" : "=l"(r) : "f"(v)); return r;
}
__device__ __forceinline__ void unpack2(u64 v, float& lo, float& hi) {
    asm("mov.b64 {%0,%1},%2;" : "=f"(lo), "=f"(hi) : "l"(v));
}
__device__ __forceinline__ u64 fma2(u64 a, u64 b, u64 c) {
    u64 d; asm("fma.rn.f32x2 %0,%1,%2,%3;" : "=l"(d) : "l"(a), "l"(b), "l"(c)); return d;
}
__device__ __forceinline__ u64 add2(u64 a, u64 b) {
    u64 d; asm("add.rn.f32x2 %0,%1,%2;" : "=l"(d) : "l"(a), "l"(b)); return d;
}
__device__ __forceinline__ float elu1(float x) {
    return x > 0.0f ? x : (__expf(x) - 1.0f);
}

// 32-lane reduce of 8 partials; lane ends with head lane>>2
__device__ __forceinline__ float reduce8_32(const float p[8], int lane) {
    bool b4 = (lane & 16) != 0;
    float q[4];
#pragma unroll
    for (int j = 0; j < 4; ++j) {
        float send = b4 ? p[j] : p[j + 4];
        float recv = __shfl_xor_sync(FULLMASK, send, 16);
        q[j] = (b4 ? p[j + 4] : p[j]) + recv;
    }
    bool b3 = (lane & 8) != 0;
    float r[2];
#pragma unroll
    for (int j = 0; j < 2; ++j) {
        float send = b3 ? q[j] : q[j + 2];
        float recv = __shfl_xor_sync(FULLMASK, send, 8);
        r[j] = (b3 ? q[j + 2] : q[j]) + recv;
    }
    bool b2 = (lane & 4) != 0;
    float send = b2 ? r[0] : r[1];
    float recv = __shfl_xor_sync(FULLMASK, send, 4);
    float s = (b2 ? r[1] : r[0]) + recv;
    s += __shfl_xor_sync(FULLMASK, s, 2);
    s += __shfl_xor_sync(FULLMASK, s, 1);
    return s;
}

// ---------- prep: CSR row starts (edge-parallel) + a1 (warp-per-node) ----------
__global__ __launch_bounds__(256, 8)
void prep_kernel(const int* __restrict__ seg,
                 const float* __restrict__ features,
                 const float* __restrict__ attn1,
                 int N, int E) {
    const int gtid = blockIdx.x * blockDim.x + threadIdx.x;

    if (gtid < E) {
        int s = seg[gtid];
        int p = (gtid == 0) ? -1 : seg[gtid - 1];
        for (int n = p + 1; n <= s; ++n) g_starts[n] = gtid;
        if (gtid == E - 1)
            for (int n = s + 1; n <= N; ++n) g_starts[n] = E;
    }

    const int lane = threadIdx.x & 31;
    const int n = gtid >> 5;
    if (n < N) {
        float2 f = *(const float2*)(features + (size_t)n * 64 + 2 * lane);
        float p1[8];
#pragma unroll
        for (int h = 0; h < 8; ++h) {
            float2 a = *(const float2*)(attn1 + h * 64 + 2 * lane);
            p1[h] = f.x * a.x + f.y * a.y;
        }
        float v = reduce8_32(p1, lane);
        if ((lane & 3) == 0) g_a1[n * 8 + (lane >> 2)] = v;
    }
}

// ---------- main kernel: warp per node, fully warp-local 16-edge sweeps ----------
__global__ __launch_bounds__(128, 6)
void gat_main_kernel(const float* __restrict__ emb,
                     const float* __restrict__ attn2,
                     float*       __restrict__ out,
                     int N)
{
    __shared__ float4 s_stage[NPB][16][16];   // [warp][edge][chunk], chunk idx swizzled (16KB)
    __shared__ float  s_w[NPB][16][8];        // per-warp weight mailbox (2KB)
    __shared__ float4 s_a2[8][16];            // attn2 [head][16B-chunk] (2KB)

    const int tid  = threadIdx.x;
    const int lane = tid & 31;
    const int wid  = tid >> 5;

    // attn2 -> smem (128 float4s, one per thread)
    {
        const float4* a2f4 = (const float4*)attn2;
        s_a2[tid >> 4][tid & 15] = a2f4[tid];
    }
    __syncthreads();                          // only block barrier in the kernel

    const int n = blockIdx.x * NPB + wid;
    if (n >= N) return;

    const int s0 = g_starts[n];
    const int e0 = g_starts[n + 1];

    const int el = lane & 15;                 // this lane's edge slot within a sweep
    const int hh = lane >> 4;                 // head half (0: heads 0-3, 1: heads 4-7)

    // a1 loop-invariant: all edges of this warp belong to node n
    const float4 a1v = *(const float4*)(g_a1 + n * 8 + hh * 4);

    const float4* __restrict__ ef4 = (const float4*)emb;
    const u64 Z = 0ull;

    u64 accx[4], accy[4], dnp[4];             // head-pair packed accumulators
#pragma unroll
    for (int hp = 0; hp < 4; ++hp) { accx[hp] = Z; accy[hp] = Z; dnp[hp] = Z; }

    for (int eb = s0; eb < e0; eb += 16) {
        // ---- stage 16 edges x 256B (coalesced LDG.128, swizzled STS.128) ----
#pragma unroll
        for (int it = 0; it < 8; ++it) {
            int idx = it * 32 + lane;
            int e = idx >> 4, c = idx & 15;
            int ge = min(eb + e, e0 - 1);
            s_stage[wid][e][c ^ e] = ef4[(size_t)ge * 16 + c];
        }
        __syncwarp();

        // ---- dot: lane = (edge el, heads [4hh,4hh+4)), all 64 dims from smem ----
        u64 d0 = Z, d1 = Z, d2 = Z, d3 = Z;
#pragma unroll
        for (int c = 0; c < 16; ++c) {
            float4 ev = s_stage[wid][el][c ^ el];
            u64 ep0 = pack2(ev.x, ev.y), ep1 = pack2(ev.z, ev.w);
            float4 a20 = s_a2[hh * 4 + 0][c];
            float4 a21 = s_a2[hh * 4 + 1][c];
            float4 a22 = s_a2[hh * 4 + 2][c];
            float4 a23 = s_a2[hh * 4 + 3][c];
            d0 = fma2(ep0, pack2(a20.x, a20.y), d0);
            d1 = fma2(ep0, pack2(a21.x, a21.y), d1);
            d2 = fma2(ep0, pack2(a22.x, a22.y), d2);
            d3 = fma2(ep0, pack2(a23.x, a23.y), d3);
            d0 = fma2(ep1, pack2(a20.z, a20.w), d0);
            d1 = fma2(ep1, pack2(a21.z, a21.w), d1);
            d2 = fma2(ep1, pack2(a22.z, a22.w), d2);
            d3 = fma2(ep1, pack2(a23.z, a23.w), d3);
        }
        float l0, h0, l1, h1, l2, h2, l3, h3;
        unpack2(d0, l0, h0); unpack2(d1, l1, h1);
        unpack2(d2, l2, h2); unpack2(d3, l3, h3);
        float sc0 = a1v.x + (l0 + h0);
        float sc1 = a1v.y + (l1 + h1);
        float sc2 = a1v.z + (l2 + h2);
        float sc3 = a1v.w + (l3 + h3);
        sc0 = fmaxf(sc0, 0.2f * sc0);          // leaky relu
        sc1 = fmaxf(sc1, 0.2f * sc1);
        sc2 = fmaxf(sc2, 0.2f * sc2);
        sc3 = fmaxf(sc3, 0.2f * sc3);
        // no-max softmax: scores bounded, exp cannot overflow fp32
        const bool valid = (eb + el) < e0;
        float4 wv;
        wv.x = valid ? __expf(sc0) : 0.0f;
        wv.y = valid ? __expf(sc1) : 0.0f;
        wv.z = valid ? __expf(sc2) : 0.0f;
        wv.w = valid ? __expf(sc3) : 0.0f;
        *(float4*)&s_w[wid][el][hh * 4] = wv;
        __syncwarp();

        // ---- agg: emb pairs straight from the stage (LDS.64, conflict-free) ----
        const int m = min(16, e0 - eb);        // warp-uniform
#pragma unroll 2
        for (int e = 0; e < m; ++e) {
            const float4* wrow = (const float4*)s_w[wid][e];
            float4 wa = wrow[0];               // heads 0-3 (broadcast LDS.128)
            float4 wb = wrow[1];               // heads 4-7
            const char* cp = (const char*)&s_stage[wid][e][(lane >> 1) ^ e];
            u64 c2 = *(const u64*)(cp + (lane & 1) * 8);   // {emb[2*lane], emb[2*lane+1]}
            float clo, chi; unpack2(c2, clo, chi);
            u64 w01 = pack2(wa.x, wa.y), w23 = pack2(wa.z, wa.w);
            u64 w45 = pack2(wb.x, wb.y), w67 = pack2(wb.z, wb.w);
            dnp[0] = add2(dnp[0], w01);
            dnp[1] = add2(dnp[1], w23);
            dnp[2] = add2(dnp[2], w45);
            dnp[3] = add2(dnp[3], w67);
            u64 cx = splat2(clo), cy = splat2(chi);
            accx[0] = fma2(w01, cx, accx[0]);  accy[0] = fma2(w01, cy, accy[0]);
            accx[1] = fma2(w23, cx, accx[1]);  accy[1] = fma2(w23, cy, accy[1]);
            accx[2] = fma2(w45, cx, accx[2]);  accy[2] = fma2(w45, cy, accy[2]);
            accx[3] = fma2(w67, cx, accx[3]);  accy[3] = fma2(w67, cy, accy[3]);
        }
        __syncwarp();                          // stage/w reused next sweep
    }

    // ---- finalize: normalize, ELU, store ----
    float* op = out + (size_t)n * 512 + 2 * lane;
#pragma unroll
    for (int hp = 0; hp < 4; ++hp) {
        float dA, dB; unpack2(dnp[hp], dA, dB);
        float iA = dA > 0.0f ? __frcp_rn(dA) : 1.0f;
        float iB = dB > 0.0f ? __frcp_rn(dB) : 1.0f;
        float xA, xB, yA, yB;
        unpack2(accx[hp], xA, xB);
        unpack2(accy[hp], yA, yB);
        *(float2*)(op + (2 * hp)     * 64) = make_float2(elu1(xA * iA), elu1(yA * iA));
        *(float2*)(op + (2 * hp + 1) * 64) = make_float2(elu1(xB * iB), elu1(yB * iB));
    }
}

extern "C" void kernel_launch(void* const* d_in, const int* in_sizes, int n_in,
                              void* d_out, int out_size) {
    const float* features = (const float*)d_in[0];
    const float* emb      = (const float*)d_in[1];
    const float* attn1    = (const float*)d_in[2];
    const float* attn2    = (const float*)d_in[3];
    const int*   seg      = (const int*)d_in[4];
    float* out = (float*)d_out;

    int N = in_sizes[0] / 64;    // 50000
    int E = in_sizes[4];         // 1250000

    int prepThreads = (N * 32 > E) ? N * 32 : E;
    prep_kernel<<<(prepThreads + 255) / 256, 256>>>(seg, features, attn1, N, E);

    int blocks = (N + NPB - 1) / NPB;
    gat_main_kernel<<<blocks, NPB * 32>>>(emb, attn2, out, N);
}